// round 7
// baseline (speedup 1.0000x reference)
#include <cuda_runtime.h>
#include <cuda_fp16.h>
#include <cstdint>

// ---------------------------------------------------------------------------
// Problem constants
// ---------------------------------------------------------------------------
#define NB    8
#define LSEQ  2048
#define KDIM  1024
#define EDIM  1024
#define MTOT  (NB * LSEQ)

// ---------------------------------------------------------------------------
// GEMM tiling — single-pass fp16 mma.sync, BK=64, 3-stage ring, 1 sync/iter
// ---------------------------------------------------------------------------
#define BM 128
#define BN 128
#define BK 64
#define NCHUNK (KDIM / BK)              // 16
#define THREADS 256
#define STAGES 3

#define TILE_BYTES 16384                // 128 rows x 128B
#define STAGE_BYTES (2 * TILE_BYTES)    // A + B = 32 KB
#define GEMM_SMEM (STAGES * STAGE_BYTES)

// ---------------------------------------------------------------------------
// Scratch (device globals — allocation-free rule)
// ---------------------------------------------------------------------------
__device__ __half g_A[(size_t)MTOT * KDIM];
__device__ __half g_B[(size_t)EDIM * KDIM];
__device__ float g_part[NB * 16 * KDIM];
__device__ float g_x2sum[NB * KDIM];
__device__ float g_bias2[NB * EDIM];

// ---------------------------------------------------------------------------
// PTX helpers (portable sm_80+)
// ---------------------------------------------------------------------------
__device__ __forceinline__ uint32_t smem_u32(const void* p) {
    uint32_t a;
    asm("{ .reg .u64 t; cvta.to.shared.u64 t, %1; cvt.u32.u64 %0, t; }"
        : "=r"(a) : "l"(p));
    return a;
}

__device__ __forceinline__ void cp16(uint32_t dst, const void* src) {
    asm volatile("cp.async.cg.shared.global [%0], [%1], 16;"
                 :: "r"(dst), "l"(src));
}
#define CP_COMMIT() asm volatile("cp.async.commit_group;" ::: "memory")
#define CP_WAIT(n)  asm volatile("cp.async.wait_group %0;" :: "n"(n) : "memory")

__device__ __forceinline__ void ldm_x4(uint32_t& d0, uint32_t& d1,
                                       uint32_t& d2, uint32_t& d3,
                                       uint32_t addr) {
    asm volatile("ldmatrix.sync.aligned.m8n8.x4.shared.b16 {%0,%1,%2,%3}, [%4];"
                 : "=r"(d0), "=r"(d1), "=r"(d2), "=r"(d3) : "r"(addr));
}

__device__ __forceinline__ void mma16816(float c[4], const uint32_t a[4],
                                         const uint32_t b[2]) {
    asm volatile(
        "mma.sync.aligned.m16n8k16.row.col.f32.f16.f16.f32 "
        "{%0,%1,%2,%3}, {%4,%5,%6,%7}, {%8,%9}, {%0,%1,%2,%3};"
        : "+f"(c[0]), "+f"(c[1]), "+f"(c[2]), "+f"(c[3])
        : "r"(a[0]), "r"(a[1]), "r"(a[2]), "r"(a[3]), "r"(b[0]), "r"(b[1]));
}

// 128B-row XOR swizzle: chunk16 in 0..7; conflict-free ldmatrix 8-row reads
__device__ __forceinline__ uint32_t swz128(int row, int chunk16) {
    return (uint32_t)((row << 7) + ((chunk16 ^ (row & 7)) << 4));
}

// ---------------------------------------------------------------------------
// Kernel 1: x1 (f32) -> fp16
// ---------------------------------------------------------------------------
__global__ void __launch_bounds__(256) split_x1_kernel(const float4* __restrict__ x) {
    int i = blockIdx.x * 256 + threadIdx.x;
    float4 v = x[i];
    __half2* p = reinterpret_cast<__half2*>(g_A);
    p[2 * i]     = __floats2half2_rn(v.x, v.y);
    p[2 * i + 1] = __floats2half2_rn(v.z, v.w);
}

// ---------------------------------------------------------------------------
// Kernel 2: W1 = W[:, :1024] (f32) -> fp16, [e,k] row-major
// ---------------------------------------------------------------------------
__global__ void __launch_bounds__(256) split_W_kernel(const float* __restrict__ W) {
    int i = blockIdx.x * 256 + threadIdx.x;
    int e  = i >> 8;
    int k4 = i & 255;
    float4 v = *reinterpret_cast<const float4*>(W + (size_t)e * 2048 + k4 * 4);
    size_t o = (size_t)e * 1024 + k4 * 4;
    __half2* p = reinterpret_cast<__half2*>(g_B + o);
    p[0] = __floats2half2_rn(v.x, v.y);
    p[1] = __floats2half2_rn(v.z, v.w);
}

// ---------------------------------------------------------------------------
// Kernel 3: pooling partials over x2 (deterministic, no atomics)
// ---------------------------------------------------------------------------
__global__ void __launch_bounds__(256) pool_x2_kernel(const float* __restrict__ x2) {
    int b = blockIdx.x >> 4;
    int s = blockIdx.x & 15;
    const float* base = x2 + ((size_t)b * LSEQ + s * 128) * KDIM;
    for (int d = threadIdx.x; d < KDIM; d += 256) {
        float acc = 0.f;
        #pragma unroll 8
        for (int l = 0; l < 128; l++) acc += base[(size_t)l * KDIM + d];
        g_part[(size_t)blockIdx.x * KDIM + d] = acc;
    }
}

__global__ void __launch_bounds__(256) reduce_pool_kernel() {
    int i = blockIdx.x * 256 + threadIdx.x;
    int b = i >> 10, d = i & 1023;
    float acc = 0.f;
    #pragma unroll
    for (int s = 0; s < 16; s++) acc += g_part[((size_t)b * 16 + s) * KDIM + d];
    g_x2sum[i] = acc;
}

// ---------------------------------------------------------------------------
// Kernel 4: bias2[b,e] = dot(x2sum[b,:], W2[e,:]) / 2048 + bias[e]
// ---------------------------------------------------------------------------
__global__ void __launch_bounds__(256) part2_kernel(const float* __restrict__ W,
                                                    const float* __restrict__ bias) {
    int warp = threadIdx.x >> 5, lane = threadIdx.x & 31;
    int e = blockIdx.x;
    const float* wrow = W + (size_t)e * 2048 + 1024;
    const float* xs = g_x2sum + warp * 1024;
    float acc = 0.f;
    #pragma unroll 8
    for (int k = lane; k < 1024; k += 32) acc += xs[k] * wrow[k];
    #pragma unroll
    for (int o = 16; o; o >>= 1) acc += __shfl_xor_sync(0xFFFFFFFFu, acc, o);
    if (lane == 0) g_bias2[warp * 1024 + e] = acc * (1.0f / 2048.0f) + bias[e];
}

// ---------------------------------------------------------------------------
// Kernel 5: main GEMM — fp16 mma.sync m16n8k16, BK=64, 3-stage, 1 sync/iter
// out[m, e] = x1[m,:]·W1[e,:] + bias2[m>>11, e]
// ---------------------------------------------------------------------------
__global__ void __launch_bounds__(THREADS) gemm_kernel(float* __restrict__ out) {
    extern __shared__ __align__(1024) char smem[];

    const int tid    = threadIdx.x;
    const int lane   = tid & 31;
    const int wid    = tid >> 5;
    const int warp_m = wid & 1;
    const int warp_n = wid >> 1;
    const int mBase  = blockIdx.y * BM;
    const int nBase  = blockIdx.x * BN;

    const uint32_t sbase = smem_u32(smem);
    const uint32_t st0 = sbase;
    const uint32_t st1 = sbase + STAGE_BYTES;
    const uint32_t st2 = sbase + 2 * STAGE_BYTES;

    const __half* gA = g_A + (size_t)mBase * KDIM;
    const __half* gB = g_B + (size_t)nBase * KDIM;

    // cp.async mapping: 128 rows x 8 chunks(16B) per tile; 4 chunks/thread
    const int lr  = tid >> 1;
    const int lc0 = (tid & 1) * 4;

    const __half* aRowG = gA + (size_t)lr * KDIM;
    const __half* bRowG = gB + (size_t)lr * KDIM;
    uint32_t ldOff[4];
    #pragma unroll
    for (int i = 0; i < 4; i++) ldOff[i] = swz128(lr, lc0 + i);

    auto loadChunk = [&](int kc, uint32_t stageAddr) {
        const int koff = kc * BK;
        #pragma unroll
        for (int i = 0; i < 4; i++) {
            int c = lc0 + i;
            cp16(stageAddr + ldOff[i],              aRowG + koff + c * 8);
            cp16(stageAddr + TILE_BYTES + ldOff[i], bRowG + koff + c * 8);
        }
    };

    // ldmatrix lane base offsets
    const int matId = lane >> 3;
    const int mrow  = lane & 7;
    const int a_row = warp_m * 64 + (matId & 1) * 8 + mrow;
    const int a_kc  = matId >> 1;
    const int b_row = warp_n * 32 + (matId >> 1) * 8 + mrow;
    const int b_kc  = matId & 1;

    uint32_t aOff[4][4], bOff[4][2];
    #pragma unroll
    for (int ks = 0; ks < 4; ks++) {
        #pragma unroll
        for (int mi = 0; mi < 4; mi++)
            aOff[ks][mi] = swz128(a_row + mi * 16, ks * 2 + a_kc);
        #pragma unroll
        for (int p = 0; p < 2; p++)
            bOff[ks][p] = swz128(b_row + p * 16, ks * 2 + b_kc);
    }

    float acc[4][4][4];
    #pragma unroll
    for (int mi = 0; mi < 4; mi++)
        #pragma unroll
        for (int ni = 0; ni < 4; ni++)
            #pragma unroll
            for (int q = 0; q < 4; q++) acc[mi][ni][q] = 0.f;

    // prologue: fill stages 0 and 1
    loadChunk(0, st0); CP_COMMIT();
    loadChunk(1, st1); CP_COMMIT();

    uint32_t sCompute = st0;
    uint32_t sLoad    = st2;
    uint32_t sMid     = st1;

    for (int kc = 0; kc < NCHUNK; kc++) {
        CP_WAIT(1);                 // chunk kc resident in sCompute
        __syncthreads();            // everyone finished reading sLoad last iter

        if (kc + 2 < NCHUNK) loadChunk(kc + 2, sLoad);
        CP_COMMIT();                // empty group in tail keeps count exact

        const uint32_t aS = sCompute;
        const uint32_t bS = sCompute + TILE_BYTES;

        #pragma unroll
        for (int ks = 0; ks < 4; ks++) {
            uint32_t a[4][4], b[4][2];
            #pragma unroll
            for (int mi = 0; mi < 4; mi++)
                ldm_x4(a[mi][0], a[mi][1], a[mi][2], a[mi][3],
                       aS + aOff[ks][mi]);
            #pragma unroll
            for (int p = 0; p < 2; p++)
                ldm_x4(b[2*p][0], b[2*p][1], b[2*p+1][0], b[2*p+1][1],
                       bS + bOff[ks][p]);
            #pragma unroll
            for (int mi = 0; mi < 4; mi++)
                #pragma unroll
                for (int ni = 0; ni < 4; ni++)
                    mma16816(acc[mi][ni], a[mi], b[ni]);
        }

        uint32_t t = sCompute;      // rotate ring: compute <- mid <- load <- old compute
        sCompute = sMid;
        sMid     = sLoad;
        sLoad    = t;
    }

    // epilogue: add bias2 (per-batch pooled term + b), write fp32
    const int g = lane >> 2, t4 = lane & 3;
    const int batch = mBase >> 11;
    const float* bias = g_bias2 + (size_t)batch * EDIM;

    #pragma unroll
    for (int ni = 0; ni < 4; ni++) {
        int col = nBase + warp_n * 32 + ni * 8 + 2 * t4;
        float2 bv = *reinterpret_cast<const float2*>(bias + col);
        #pragma unroll
        for (int mi = 0; mi < 4; mi++) {
            int m0 = mBase + warp_m * 64 + mi * 16 + g;
            float2 o0 = make_float2(acc[mi][ni][0] + bv.x, acc[mi][ni][1] + bv.y);
            float2 o1 = make_float2(acc[mi][ni][2] + bv.x, acc[mi][ni][3] + bv.y);
            *reinterpret_cast<float2*>(out + (size_t)m0 * EDIM + col) = o0;
            *reinterpret_cast<float2*>(out + (size_t)(m0 + 8) * EDIM + col) = o1;
        }
    }
}

// ---------------------------------------------------------------------------
// Launch
// ---------------------------------------------------------------------------
extern "C" void kernel_launch(void* const* d_in, const int* in_sizes, int n_in,
                              void* d_out, int out_size) {
    const float* x1   = (const float*)d_in[0];
    const float* x2   = (const float*)d_in[1];
    const float* W    = (const float*)d_in[2];
    const float* bias = (const float*)d_in[3];
    float* out = (float*)d_out;

    cudaFuncSetAttribute(gemm_kernel, cudaFuncAttributeMaxDynamicSharedMemorySize,
                         GEMM_SMEM);

    split_x1_kernel<<<(MTOT * KDIM) / 4 / 256, 256>>>(
        reinterpret_cast<const float4*>(x1));
    split_W_kernel<<<(EDIM * KDIM) / 4 / 256, 256>>>(W);
    pool_x2_kernel<<<NB * 16, 256>>>(x2);
    reduce_pool_kernel<<<(NB * KDIM) / 256, 256>>>();
    part2_kernel<<<EDIM, 256>>>(W, bias);
    gemm_kernel<<<dim3(EDIM / BN, MTOT / BM), THREADS, GEMM_SMEM>>>(out);
}

// round 8
// speedup vs baseline: 1.1426x; 1.1426x over previous
#include <cuda_runtime.h>
#include <cuda_fp16.h>
#include <cstdint>

// ---------------------------------------------------------------------------
// Problem constants
// ---------------------------------------------------------------------------
#define NB    8
#define LSEQ  2048
#define KDIM  1024
#define EDIM  1024
#define MTOT  (NB * LSEQ)

// ---------------------------------------------------------------------------
// GEMM tiling — single-pass fp16 mma.sync, BK=32, 4-stage (proven R4 base)
// ---------------------------------------------------------------------------
#define BM 128
#define BN 128
#define BK 32
#define NCHUNK (KDIM / BK)   // 32
#define THREADS 256
#define STAGES 4

#define TILE_BYTES 8192                  // 128 rows x 64B (32 fp16, swizzled)
#define STAGE_BYTES (2 * TILE_BYTES)     // A, B
#define GEMM_SMEM (STAGES * STAGE_BYTES) // 64 KB

// fused preproc grid split
#define NBLK_X1   ((MTOT * KDIM) / 4 / 256)   // 16384
#define NBLK_W    ((EDIM * KDIM) / 4 / 256)   // 1024
#define NBLK_POOL (NB * 16)                   // 128
#define NBLK_PRE  (NBLK_X1 + NBLK_W + NBLK_POOL)

// ---------------------------------------------------------------------------
// Scratch (device globals — allocation-free rule)
// ---------------------------------------------------------------------------
__device__ __half g_A[(size_t)MTOT * KDIM];    // 32 MB: fp16(x1)
__device__ __half g_B[(size_t)EDIM * KDIM];    //  2 MB: fp16(W1), [e,k]
__device__ float g_part[NB * 16 * KDIM];
__device__ float g_x2sum[NB * KDIM];
__device__ float g_bias2[NB * EDIM];           // part2/L + b

// ---------------------------------------------------------------------------
// PTX helpers (portable sm_80+)
// ---------------------------------------------------------------------------
__device__ __forceinline__ uint32_t smem_u32(const void* p) {
    uint32_t a;
    asm("{ .reg .u64 t; cvta.to.shared.u64 t, %1; cvt.u32.u64 %0, t; }"
        : "=r"(a) : "l"(p));
    return a;
}

__device__ __forceinline__ void cp16(uint32_t dst, const void* src) {
    asm volatile("cp.async.cg.shared.global [%0], [%1], 16;"
                 :: "r"(dst), "l"(src));
}
#define CP_COMMIT() asm volatile("cp.async.commit_group;" ::: "memory")
#define CP_WAIT(n)  asm volatile("cp.async.wait_group %0;" :: "n"(n) : "memory")

__device__ __forceinline__ void ldm_x4(uint32_t& d0, uint32_t& d1,
                                       uint32_t& d2, uint32_t& d3,
                                       uint32_t addr) {
    asm volatile("ldmatrix.sync.aligned.m8n8.x4.shared.b16 {%0,%1,%2,%3}, [%4];"
                 : "=r"(d0), "=r"(d1), "=r"(d2), "=r"(d3) : "r"(addr));
}

__device__ __forceinline__ void mma16816(float c[4], const uint32_t a[4],
                                         const uint32_t b[2]) {
    asm volatile(
        "mma.sync.aligned.m16n8k16.row.col.f32.f16.f16.f32 "
        "{%0,%1,%2,%3}, {%4,%5,%6,%7}, {%8,%9}, {%0,%1,%2,%3};"
        : "+f"(c[0]), "+f"(c[1]), "+f"(c[2]), "+f"(c[3])
        : "r"(a[0]), "r"(a[1]), "r"(a[2]), "r"(a[3]), "r"(b[0]), "r"(b[1]));
}

// XOR swizzle: 64B rows, 16B chunks; conflict-free for ldmatrix 8-row reads
__device__ __forceinline__ uint32_t swz(int row, int chunk16) {
    return (uint32_t)(row * 64 + ((chunk16 ^ ((row >> 1) & 3)) * 16));
}

// ---------------------------------------------------------------------------
// Fused preprocessing: split_x1 | split_W | pool_x2 partials (independent)
// ---------------------------------------------------------------------------
__global__ void __launch_bounds__(256) fused_pre_kernel(
    const float4* __restrict__ x1v,
    const float*  __restrict__ W,
    const float*  __restrict__ x2) {
    int bx = blockIdx.x;
    if (bx < NBLK_X1) {
        // --- x1 (f32) -> fp16 ---
        int i = bx * 256 + threadIdx.x;
        float4 v = x1v[i];
        __half2* p = reinterpret_cast<__half2*>(g_A);
        p[2 * i]     = __floats2half2_rn(v.x, v.y);
        p[2 * i + 1] = __floats2half2_rn(v.z, v.w);
    } else if (bx < NBLK_X1 + NBLK_W) {
        // --- W1 = W[:, :1024] -> fp16, [e,k] row-major ---
        int i = (bx - NBLK_X1) * 256 + threadIdx.x;
        int e  = i >> 8;
        int k4 = i & 255;
        float4 v = *reinterpret_cast<const float4*>(W + (size_t)e * 2048 + k4 * 4);
        size_t o = (size_t)e * 1024 + k4 * 4;
        __half2* p = reinterpret_cast<__half2*>(g_B + o);
        p[0] = __floats2half2_rn(v.x, v.y);
        p[1] = __floats2half2_rn(v.z, v.w);
    } else {
        // --- pooling partials over x2 (deterministic, no atomics) ---
        int pb = bx - NBLK_X1 - NBLK_W;          // 0..127
        int b = pb >> 4;
        int s = pb & 15;
        const float* base = x2 + ((size_t)b * LSEQ + s * 128) * KDIM;
        for (int d = threadIdx.x; d < KDIM; d += 256) {
            float acc = 0.f;
            #pragma unroll 8
            for (int l = 0; l < 128; l++) acc += base[(size_t)l * KDIM + d];
            g_part[(size_t)pb * KDIM + d] = acc;
        }
    }
}

__global__ void __launch_bounds__(256) reduce_pool_kernel() {
    int i = blockIdx.x * 256 + threadIdx.x;       // 8192
    int b = i >> 10, d = i & 1023;
    float acc = 0.f;
    #pragma unroll
    for (int s = 0; s < 16; s++) acc += g_part[((size_t)b * 16 + s) * KDIM + d];
    g_x2sum[i] = acc;
}

// ---------------------------------------------------------------------------
// bias2[b,e] = dot(x2sum[b,:], W2[e,:]) / 2048 + bias[e]
// ---------------------------------------------------------------------------
__global__ void __launch_bounds__(256) part2_kernel(const float* __restrict__ W,
                                                    const float* __restrict__ bias) {
    int warp = threadIdx.x >> 5, lane = threadIdx.x & 31;
    int e = blockIdx.x;
    const float* wrow = W + (size_t)e * 2048 + 1024;
    const float* xs = g_x2sum + warp * 1024;
    float acc = 0.f;
    #pragma unroll 8
    for (int k = lane; k < 1024; k += 32) acc += xs[k] * wrow[k];
    #pragma unroll
    for (int o = 16; o; o >>= 1) acc += __shfl_xor_sync(0xFFFFFFFFu, acc, o);
    if (lane == 0) g_bias2[warp * 1024 + e] = acc * (1.0f / 2048.0f) + bias[e];
}

// ---------------------------------------------------------------------------
// Main GEMM — fp16 mma.sync m16n8k16, BK=32, 4-stage (R4 structure),
// with both ks fragment batches loaded before any MMA (latency hiding).
// out[m, e] = x1[m,:]·W1[e,:] + bias2[m>>11, e]
// ---------------------------------------------------------------------------
__global__ void __launch_bounds__(THREADS) gemm_kernel(float* __restrict__ out) {
    extern __shared__ __align__(1024) char smem[];

    const int tid    = threadIdx.x;
    const int lane   = tid & 31;
    const int wid    = tid >> 5;
    const int warp_m = wid & 1;        // 0..1 (M = 64 per warp)
    const int warp_n = wid >> 1;       // 0..3 (N = 32 per warp)
    const int mBase  = blockIdx.y * BM;
    const int nBase  = blockIdx.x * BN;

    const uint32_t sbase = smem_u32(smem);

    const __half* gA = g_A + (size_t)mBase * KDIM;
    const __half* gB = g_B + (size_t)nBase * KDIM;

    const int lr0 = tid >> 2;          // row (0..63), +64 on second pass
    const int lc  = tid & 3;           // 16B chunk in row

    auto loadChunk = [&](int kc, int s) {
        const uint32_t aDst = sbase + s * STAGE_BYTES;
        const uint32_t bDst = aDst + TILE_BYTES;
        const int koff = kc * BK;
        #pragma unroll
        for (int i = 0; i < 2; i++) {
            int r = lr0 + i * 64;
            uint32_t off = swz(r, lc);
            size_t g = (size_t)r * KDIM + koff + lc * 8;
            cp16(aDst + off, gA + g);
            cp16(bDst + off, gB + g);
        }
    };

    // ldmatrix lane base offsets
    const int matId = lane >> 3;
    const int mrow  = lane & 7;
    const int a_row = warp_m * 64 + (matId & 1) * 8 + mrow;  // + mi*16
    const int a_kc  = matId >> 1;                            // + ks*2
    const int b_row = warp_n * 32 + (matId >> 1) * 8 + mrow; // + p*16
    const int b_kc  = matId & 1;                             // + ks*2

    uint32_t aOff[2][4], bOff[2][2];
    #pragma unroll
    for (int ks = 0; ks < 2; ks++) {
        #pragma unroll
        for (int mi = 0; mi < 4; mi++)
            aOff[ks][mi] = swz(a_row + mi * 16, ks * 2 + a_kc);
        #pragma unroll
        for (int p = 0; p < 2; p++)
            bOff[ks][p] = swz(b_row + p * 16, ks * 2 + b_kc);
    }

    float acc[4][4][4];
    #pragma unroll
    for (int mi = 0; mi < 4; mi++)
        #pragma unroll
        for (int ni = 0; ni < 4; ni++)
            #pragma unroll
            for (int q = 0; q < 4; q++) acc[mi][ni][q] = 0.f;

    // prologue: fill 3 stages
    loadChunk(0, 0); CP_COMMIT();
    loadChunk(1, 1); CP_COMMIT();
    loadChunk(2, 2); CP_COMMIT();

    for (int kc = 0; kc < NCHUNK; kc++) {
        const int s = kc & (STAGES - 1);
        if (kc + 3 < NCHUNK) loadChunk(kc + 3, (kc + 3) & (STAGES - 1));
        CP_COMMIT();                   // empty group in tail keeps count exact
        CP_WAIT(3);                    // group kc complete
        __syncthreads();

        const uint32_t aS = sbase + s * STAGE_BYTES;
        const uint32_t bS = aS + TILE_BYTES;

        // load ALL fragments for both ks before any MMA: the second batch's
        // LDS latency hides under the first batch's 16 MMAs.
        uint32_t a[2][4][4], b[2][4][2];
        #pragma unroll
        for (int ks = 0; ks < 2; ks++) {
            #pragma unroll
            for (int mi = 0; mi < 4; mi++)
                ldm_x4(a[ks][mi][0], a[ks][mi][1], a[ks][mi][2], a[ks][mi][3],
                       aS + aOff[ks][mi]);
            #pragma unroll
            for (int p = 0; p < 2; p++)
                ldm_x4(b[ks][2*p][0], b[ks][2*p][1],
                       b[ks][2*p+1][0], b[ks][2*p+1][1],
                       bS + bOff[ks][p]);
        }
        #pragma unroll
        for (int ks = 0; ks < 2; ks++)
            #pragma unroll
            for (int mi = 0; mi < 4; mi++)
                #pragma unroll
                for (int ni = 0; ni < 4; ni++)
                    mma16816(acc[mi][ni], a[ks][mi], b[ks][ni]);

        __syncthreads();
    }

    // epilogue: add bias2 (per-batch pooled term + b), write fp32
    const int g = lane >> 2, t = lane & 3;
    const int batch = mBase >> 11;                 // same for whole CTA
    const float* bias = g_bias2 + (size_t)batch * EDIM;

    #pragma unroll
    for (int ni = 0; ni < 4; ni++) {
        int col = nBase + warp_n * 32 + ni * 8 + 2 * t;
        float2 bv = *reinterpret_cast<const float2*>(bias + col);
        #pragma unroll
        for (int mi = 0; mi < 4; mi++) {
            int m0 = mBase + warp_m * 64 + mi * 16 + g;
            float2 o0 = make_float2(acc[mi][ni][0] + bv.x, acc[mi][ni][1] + bv.y);
            float2 o1 = make_float2(acc[mi][ni][2] + bv.x, acc[mi][ni][3] + bv.y);
            *reinterpret_cast<float2*>(out + (size_t)m0 * EDIM + col) = o0;
            *reinterpret_cast<float2*>(out + (size_t)(m0 + 8) * EDIM + col) = o1;
        }
    }
}

// ---------------------------------------------------------------------------
// Launch
// ---------------------------------------------------------------------------
extern "C" void kernel_launch(void* const* d_in, const int* in_sizes, int n_in,
                              void* d_out, int out_size) {
    const float* x1   = (const float*)d_in[0];
    const float* x2   = (const float*)d_in[1];
    const float* W    = (const float*)d_in[2];
    const float* bias = (const float*)d_in[3];
    float* out = (float*)d_out;

    cudaFuncSetAttribute(gemm_kernel, cudaFuncAttributeMaxDynamicSharedMemorySize,
                         GEMM_SMEM);

    fused_pre_kernel<<<NBLK_PRE, 256>>>(
        reinterpret_cast<const float4*>(x1), W, x2);
    reduce_pool_kernel<<<(NB * KDIM) / 256, 256>>>();
    part2_kernel<<<EDIM, 256>>>(W, bias);
    gemm_kernel<<<dim3(EDIM / BN, MTOT / BM), THREADS, GEMM_SMEM>>>(out);
}